// round 10
// baseline (speedup 1.0000x reference)
#include <cuda_runtime.h>
#include <cstdint>

#define UNITSN   64
#define GATES    256        // 4*UNITS
#define TSTEPS   100
#define FEAT     3
#define B_TOTAL  16384

#define CTA_THREADS    384                         // 12 warps, 1 CTA/SM
#define WARPS_PER_CTA  12
#define ROWS_PER_WARP  8
#define NUM_UNITS      (B_TOTAL / ROWS_PER_WARP)   // 2048 work units
#define GRID_CTAS      148                         // persistent, 1 per SM

// ---- shared memory layout (floats) ----
#define OFF_U    0            // 64*256      = 16384
#define OFF_W1   16384        // 64*64       = 4096
#define OFF_W    20480        // 3*256       = 768
#define OFF_B    21248        // 256
#define OFF_B1   21504        // 64
#define OFF_W2   21568        // 64*5        = 320
#define OFF_B2   21888        // 8 (padded)
#define OFF_H    21896        // 96 rows * 128 (duplicated h) = 12288
#define SMEM_FLOATS 34184
#define SMEM_BYTES  (SMEM_FLOATS * 4)   // 136736 B -> 1 CTA/SM

// ---- scratch (device globals; no allocation) ----
__device__ int g_len[B_TOTAL];
__device__ int g_perm[B_TOTAL];
__device__ int g_work;

// ---- f32x2 helpers ----
__device__ __forceinline__ unsigned long long fma2(unsigned long long a,
                                                   unsigned long long b,
                                                   unsigned long long c) {
    unsigned long long d;
    asm("fma.rn.f32x2 %0, %1, %2, %3;" : "=l"(d) : "l"(a), "l"(b), "l"(c));
    return d;
}
__device__ __forceinline__ unsigned long long dup2(float v) {
    unsigned long long d;
    asm("mov.b64 %0, {%1, %1};" : "=l"(d) : "f"(v));
    return d;
}
__device__ __forceinline__ float2 unpk(unsigned long long v) {
    float2 r;
    asm("mov.b64 {%0, %1}, %2;" : "=f"(r.x), "=f"(r.y) : "l"(v));
    return r;
}
__device__ __forceinline__ unsigned long long ld64(const float* p) {
    return *reinterpret_cast<const unsigned long long*>(p);
}
__device__ __forceinline__ float rcpa(float x) {
    float y; asm("rcp.approx.f32 %0, %1;" : "=f"(y) : "f"(x)); return y;
}

// ============================ pre-pass kernels ============================

// one warp per row: compute active length (last masked-true step + 1)
__global__ void k_len(const float* __restrict__ x) {
    int lane = threadIdx.x & 31;
    int wid  = threadIdx.x >> 5;
    int row  = blockIdx.x * 4 + wid;
    const float* p = x + (size_t)row * (TSTEPS * FEAT);

    auto chk = [&](int t) -> bool {
        return (p[t * 3] != 0.0f) | (p[t * 3 + 1] != 0.0f) | (p[t * 3 + 2] != 0.0f);
    };
    unsigned m0 = __ballot_sync(0xffffffffu, chk(lane));
    unsigned m1 = __ballot_sync(0xffffffffu, chk(lane + 32));
    unsigned m2 = __ballot_sync(0xffffffffu, chk(lane + 64));
    unsigned m3 = __ballot_sync(0xffffffffu, (lane + 96 < TSTEPS) ? chk(lane + 96) : false);

    if (lane == 0) {
        int len = 0;
        if      (m3) len = 96 + 32 - __clz(m3);
        else if (m2) len = 64 + 32 - __clz(m2);
        else if (m1) len = 32 + 32 - __clz(m1);
        else if (m0) len =      32 - __clz(m0);
        g_len[row] = len;
    }
}

// single CTA: counting-sort rows by descending length into g_perm; reset g_work
__global__ void k_sort() {
    __shared__ int hist[104];
    __shared__ int cur[104];
    int tid = threadIdx.x;   // 256 threads

    if (tid < 104) hist[tid] = 0;
    __syncthreads();
    for (int r = tid; r < B_TOTAL; r += 256)
        atomicAdd(&hist[100 - g_len[r]], 1);
    __syncthreads();
    if (tid == 0) {
        int run = 0;
        for (int k = 0; k <= 100; ++k) { cur[k] = run; run += hist[k]; }
        g_work = 0;
    }
    __syncthreads();
    for (int r = tid; r < B_TOTAL; r += 256) {
        int pos = atomicAdd(&cur[100 - g_len[r]], 1);
        g_perm[pos] = r;
    }
}

// padding no-op: keeps lstm_main at absolute launch index 3 (0-based) so the
// ncu capture lands on lstm_main.
__global__ void k_pad() {}

// ============================ main LSTM kernel ============================

__global__ __launch_bounds__(CTA_THREADS)   // 384 thr -> ptxas caps regs at 168
void lstm_main(const float* __restrict__ x,  const float* __restrict__ W,
               const float* __restrict__ U,  const float* __restrict__ b,
               const float* __restrict__ W1, const float* __restrict__ b1,
               const float* __restrict__ W2, const float* __restrict__ b2,
               float* __restrict__ out) {
    extern __shared__ float sm[];
    int tid = threadIdx.x;

    // ---- cooperative smem staging (once per persistent CTA) ----
    for (int i = tid; i < 4096; i += CTA_THREADS)
        ((float4*)(sm + OFF_U))[i] = ((const float4*)U)[i];
    for (int i = tid; i < 1024; i += CTA_THREADS)
        ((float4*)(sm + OFF_W1))[i] = ((const float4*)W1)[i];
    for (int i = tid; i < 192; i += CTA_THREADS)
        ((float4*)(sm + OFF_W))[i] = ((const float4*)W)[i];
    for (int i = tid; i < 64; i += CTA_THREADS)
        ((float4*)(sm + OFF_B))[i] = ((const float4*)b)[i];
    for (int i = tid; i < 16; i += CTA_THREADS)
        ((float4*)(sm + OFF_B1))[i] = ((const float4*)b1)[i];
    for (int i = tid; i < 80; i += CTA_THREADS)
        ((float4*)(sm + OFF_W2))[i] = ((const float4*)W2)[i];
    if (tid < 8) sm[OFF_B2 + tid] = (tid < 5) ? b2[tid] : 0.0f;
    __syncthreads();

    int lane = tid & 31;
    int wid  = tid >> 5;
    int slotBase = wid * ROWS_PER_WARP;                 // warp-private h slots

    // ---- hoist W pairs and b pairs into registers (valid for all units) ----
    unsigned long long Wp[3][4], bp[4];
#pragma unroll
    for (int f = 0; f < 3; ++f)
#pragma unroll
        for (int q = 0; q < 4; ++q)
            Wp[f][q] = ld64(sm + OFF_W + f * GATES + q * UNITSN + 2 * lane);
#pragma unroll
    for (int q = 0; q < 4; ++q)
        bp[q] = ld64(sm + OFF_B + q * UNITSN + 2 * lane);

    float* const hbase = sm + OFF_H + slotBase * 128;   // duplicated h rows

    const float* Ubase = sm + OFF_U + 2 * lane;

    // ================= persistent work loop: one unit = 8 rows =================
    for (;;) {
        int g = 0;
        if (lane == 0) g = atomicAdd(&g_work, 1);
        g = __shfl_sync(0xffffffffu, g, 0);
        if (g >= NUM_UNITS) break;
        int grpBase = g * ROWS_PER_WARP;

        int lenr[ROWS_PER_WARP];
        const float* xb[ROWS_PER_WARP];
#pragma unroll
        for (int r = 0; r < ROWS_PER_WARP; ++r) {
            int row  = g_perm[grpBase + r];
            lenr[r]  = g_len[row];
            xb[r]    = x + (size_t)row * (TSTEPS * FEAT);
        }
        int tmax = lenr[0];   // descending sort: first row of group is longest

        // zero h slots + c state
        float c0[ROWS_PER_WARP], c1[ROWS_PER_WARP];
#pragma unroll
        for (int r = 0; r < ROWS_PER_WARP; ++r) {
            c0[r] = 0.f; c1[r] = 0.f;
            *reinterpret_cast<float4*>(hbase + r * 128 + 4 * lane) =
                make_float4(0.f, 0.f, 0.f, 0.f);
        }
        __syncwarp();

        // ================= recurrence =================
        for (int t = 0; t < tmax; ++t) {
            unsigned long long z[ROWS_PER_WARP][4];
#pragma unroll
            for (int r = 0; r < ROWS_PER_WARP; ++r) {
                const float* p = xb[r] + t * 3;          // L1-resident after t=0
                unsigned long long d0 = dup2(p[0]);
                unsigned long long d1 = dup2(p[1]);
                unsigned long long d2 = dup2(p[2]);
#pragma unroll
                for (int q = 0; q < 4; ++q) {
                    unsigned long long a = fma2(d0, Wp[0][q], bp[q]);
                    a = fma2(d1, Wp[1][q], a);
                    z[r][q] = fma2(d2, Wp[2][q], a);
                }
            }

#pragma unroll 4
            for (int k = 0; k < UNITSN; k += 2) {
                const float* Uk = Ubase + k * GATES;
                unsigned long long u00 = ld64(Uk + 0);
                unsigned long long u01 = ld64(Uk + 64);
                unsigned long long u02 = ld64(Uk + 128);
                unsigned long long u03 = ld64(Uk + 192);
                unsigned long long u10 = ld64(Uk + 256);
                unsigned long long u11 = ld64(Uk + 320);
                unsigned long long u12 = ld64(Uk + 384);
                unsigned long long u13 = ld64(Uk + 448);
#pragma unroll
                for (int r = 0; r < ROWS_PER_WARP; ++r) {
                    ulonglong2 hh = *reinterpret_cast<const ulonglong2*>(
                        hbase + r * 128 + 2 * k);        // uniform -> broadcast
                    z[r][0] = fma2(hh.x, u00, z[r][0]);
                    z[r][1] = fma2(hh.x, u01, z[r][1]);
                    z[r][2] = fma2(hh.x, u02, z[r][2]);
                    z[r][3] = fma2(hh.x, u03, z[r][3]);
                    z[r][0] = fma2(hh.y, u10, z[r][0]);
                    z[r][1] = fma2(hh.y, u11, z[r][1]);
                    z[r][2] = fma2(hh.y, u12, z[r][2]);
                    z[r][3] = fma2(hh.y, u13, z[r][3]);
                }
            }

            __syncwarp();   // all lanes done reading h before anyone rewrites it
#pragma unroll
            for (int r = 0; r < ROWS_PER_WARP; ++r) {
                if (t < lenr[r]) {    // mask from precomputed length (no x dep)
                    float2 zi = unpk(z[r][0]);
                    float2 zf = unpk(z[r][1]);
                    float2 zg = unpk(z[r][2]);
                    float2 zo = unpk(z[r][3]);

                    // combined-RCP gates: i,f share one rcp; o and tanh(g)
                    // share one rcp. |z| <~ 8 so products stay finite.
                    float ai0 = 1.0f + __expf(-zi.x), af0 = 1.0f + __expf(-zf.x);
                    float ai1 = 1.0f + __expf(-zi.y), af1 = 1.0f + __expf(-zf.y);
                    float r0if = rcpa(ai0 * af0);
                    float r1if = rcpa(ai1 * af1);
                    float i0 = af0 * r0if, f0 = ai0 * r0if;
                    float i1 = af1 * r1if, f1 = ai1 * r1if;

                    float ao0 = 1.0f + __expf(-zo.x), dg0 = 1.0f + __expf(2.0f * zg.x);
                    float ao1 = 1.0f + __expf(-zo.y), dg1 = 1.0f + __expf(2.0f * zg.y);
                    float r0og = rcpa(ao0 * dg0);
                    float r1og = rcpa(ao1 * dg1);
                    float o0 = dg0 * r0og, g0 = fmaf(-2.0f * ao0, r0og, 1.0f);
                    float o1 = dg1 * r1og, g1 = fmaf(-2.0f * ao1, r1og, 1.0f);

                    c0[r] = f0 * c0[r] + i0 * g0;
                    c1[r] = f1 * c1[r] + i1 * g1;
                    float tc0 = fmaf(-2.0f, rcpa(1.0f + __expf(2.0f * c0[r])), 1.0f);
                    float tc1 = fmaf(-2.0f, rcpa(1.0f + __expf(2.0f * c1[r])), 1.0f);
                    float h0 = o0 * tc0;
                    float h1 = o1 * tc1;
                    *reinterpret_cast<float4*>(hbase + r * 128 + 4 * lane) =
                        make_float4(h0, h0, h1, h1);
                }
            }
            __syncwarp();   // writes visible before next step's reads
        }

        // ================= MLP head + softmax =================
        __syncwarp();
#pragma unroll 1
        for (int r = 0; r < ROWS_PER_WARP; ++r) {
            float* hr = hbase + r * 128;
            unsigned long long acc = ld64(sm + OFF_B1 + 2 * lane);
#pragma unroll 8
            for (int k = 0; k < UNITSN; ++k) {
                unsigned long long hd = ld64(hr + 2 * k);                   // (h[k],h[k])
                unsigned long long w  = ld64(sm + OFF_W1 + k * UNITSN + 2 * lane);
                acc = fma2(hd, w, acc);
            }
            float2 a = unpk(acc);
            float a0 = fmaxf(a.x, 0.f);
            float a1 = fmaxf(a.y, 0.f);
            __syncwarp();
            *reinterpret_cast<float4*>(hr + 4 * lane) = make_float4(a0, a0, a1, a1);
            __syncwarp();

            float logit = 0.0f;
            if (lane < 5) {
                logit = sm[OFF_B2 + lane];
#pragma unroll 8
                for (int k = 0; k < UNITSN; ++k)
                    logit += hr[2 * k] * sm[OFF_W2 + k * 5 + lane];
            }
            float v[5];
#pragma unroll
            for (int j = 0; j < 5; ++j) v[j] = __shfl_sync(0xffffffffu, logit, j);
            float mx = v[0];
#pragma unroll
            for (int j = 1; j < 5; ++j) mx = fmaxf(mx, v[j]);
            float s = 0.0f;
#pragma unroll
            for (int j = 0; j < 5; ++j) { v[j] = __expf(v[j] - mx); s += v[j]; }
            if (lane < 5) {
                int row = g_perm[grpBase + r];   // reload (cold path, saves regs)
                out[(size_t)row * 5 + lane] = __fdividef(v[lane], s);
            }
            __syncwarp();
        }
    }
}

// ============================ launch ============================

extern "C" void kernel_launch(void* const* d_in, const int* in_sizes, int n_in,
                              void* d_out, int out_size) {
    const float* x  = (const float*)d_in[0];
    const float* W  = (const float*)d_in[1];
    const float* U  = (const float*)d_in[2];
    const float* b  = (const float*)d_in[3];
    const float* W1 = (const float*)d_in[4];
    const float* b1 = (const float*)d_in[5];
    const float* W2 = (const float*)d_in[6];
    const float* b2 = (const float*)d_in[7];
    float* out = (float*)d_out;

    (void)in_sizes; (void)n_in; (void)out_size;

    cudaFuncSetAttribute(lstm_main, cudaFuncAttributeMaxDynamicSharedMemorySize,
                         SMEM_BYTES);

    k_len    <<<B_TOTAL / 4, 128>>>(x);
    k_sort   <<<1, 256>>>();
    k_pad    <<<1, 32>>>();
    lstm_main<<<GRID_CTAS, CTA_THREADS, SMEM_BYTES>>>(x, W, U, b, W1, b1, W2, b2, out);
}

// round 11
// speedup vs baseline: 1.0162x; 1.0162x over previous
#include <cuda_runtime.h>
#include <cstdint>

#define UNITSN   64
#define GATES    256        // 4*UNITS
#define TSTEPS   100
#define FEAT     3
#define B_TOTAL  16384

#define CTA_THREADS    320                         // 10 warps, 1 CTA/SM, 204-reg cap
#define WARPS_PER_CTA  10
#define ROWS_PER_WARP  8
#define NUM_UNITS      (B_TOTAL / ROWS_PER_WARP)   // 2048 work units
#define GRID_CTAS      148                         // persistent, 1 per SM

// ---- shared memory layout (floats) ----
#define OFF_U    0            // 64*256      = 16384
#define OFF_W1   16384        // 64*64       = 4096
#define OFF_W    20480        // 3*256       = 768
#define OFF_B    21248        // 256
#define OFF_B1   21504        // 64
#define OFF_W2   21568        // 64*5        = 320
#define OFF_B2   21888        // 8 (padded)
#define OFF_H    21896        // 80 rows * 128 (duplicated h) = 10240
#define SMEM_FLOATS 32136
#define SMEM_BYTES  (SMEM_FLOATS * 4)   // 128544 B -> 1 CTA/SM

// ---- scratch (device globals; no allocation) ----
__device__ int g_len[B_TOTAL];
__device__ int g_perm[B_TOTAL];
__device__ int g_work;

// ---- f32x2 helpers ----
__device__ __forceinline__ unsigned long long fma2(unsigned long long a,
                                                   unsigned long long b,
                                                   unsigned long long c) {
    unsigned long long d;
    asm("fma.rn.f32x2 %0, %1, %2, %3;" : "=l"(d) : "l"(a), "l"(b), "l"(c));
    return d;
}
__device__ __forceinline__ unsigned long long dup2(float v) {
    unsigned long long d;
    asm("mov.b64 %0, {%1, %1};" : "=l"(d) : "f"(v));
    return d;
}
__device__ __forceinline__ float2 unpk(unsigned long long v) {
    float2 r;
    asm("mov.b64 {%0, %1}, %2;" : "=f"(r.x), "=f"(r.y) : "l"(v));
    return r;
}
__device__ __forceinline__ unsigned long long ld64(const float* p) {
    return *reinterpret_cast<const unsigned long long*>(p);
}
// volatile shared load: prevents ptxas from hoisting loop-invariant W/b loads
// back into long-lived registers (the whole point is to keep them transient).
__device__ __forceinline__ unsigned long long lds64v(unsigned a) {
    unsigned long long v;
    asm volatile("ld.shared.b64 %0, [%1];" : "=l"(v) : "r"(a));
    return v;
}
__device__ __forceinline__ float rcpa(float x) {
    float y; asm("rcp.approx.f32 %0, %1;" : "=f"(y) : "f"(x)); return y;
}

// ============================ pre-pass kernels ============================

// one warp per row: compute active length (last masked-true step + 1)
__global__ void k_len(const float* __restrict__ x) {
    int lane = threadIdx.x & 31;
    int wid  = threadIdx.x >> 5;
    int row  = blockIdx.x * 4 + wid;
    const float* p = x + (size_t)row * (TSTEPS * FEAT);

    auto chk = [&](int t) -> bool {
        return (p[t * 3] != 0.0f) | (p[t * 3 + 1] != 0.0f) | (p[t * 3 + 2] != 0.0f);
    };
    unsigned m0 = __ballot_sync(0xffffffffu, chk(lane));
    unsigned m1 = __ballot_sync(0xffffffffu, chk(lane + 32));
    unsigned m2 = __ballot_sync(0xffffffffu, chk(lane + 64));
    unsigned m3 = __ballot_sync(0xffffffffu, (lane + 96 < TSTEPS) ? chk(lane + 96) : false);

    if (lane == 0) {
        int len = 0;
        if      (m3) len = 96 + 32 - __clz(m3);
        else if (m2) len = 64 + 32 - __clz(m2);
        else if (m1) len = 32 + 32 - __clz(m1);
        else if (m0) len =      32 - __clz(m0);
        g_len[row] = len;
    }
}

// single CTA: counting-sort rows by descending length into g_perm; reset g_work
__global__ void k_sort() {
    __shared__ int hist[104];
    __shared__ int cur[104];
    int tid = threadIdx.x;   // 256 threads

    if (tid < 104) hist[tid] = 0;
    __syncthreads();
    for (int r = tid; r < B_TOTAL; r += 256)
        atomicAdd(&hist[100 - g_len[r]], 1);
    __syncthreads();
    if (tid == 0) {
        int run = 0;
        for (int k = 0; k <= 100; ++k) { cur[k] = run; run += hist[k]; }
        g_work = 0;
    }
    __syncthreads();
    for (int r = tid; r < B_TOTAL; r += 256) {
        int pos = atomicAdd(&cur[100 - g_len[r]], 1);
        g_perm[pos] = r;
    }
}

// padding no-op: keeps lstm_main at absolute launch index 3 (0-based) so the
// ncu capture lands on lstm_main.
__global__ void k_pad() {}

// ============================ main LSTM kernel ============================

__global__ __launch_bounds__(CTA_THREADS)   // 320 thr -> 204-reg cap
void lstm_main(const float* __restrict__ x,  const float* __restrict__ W,
               const float* __restrict__ U,  const float* __restrict__ b,
               const float* __restrict__ W1, const float* __restrict__ b1,
               const float* __restrict__ W2, const float* __restrict__ b2,
               float* __restrict__ out) {
    extern __shared__ float sm[];
    int tid = threadIdx.x;

    // ---- cooperative smem staging (once per persistent CTA) ----
    for (int i = tid; i < 4096; i += CTA_THREADS)
        ((float4*)(sm + OFF_U))[i] = ((const float4*)U)[i];
    for (int i = tid; i < 1024; i += CTA_THREADS)
        ((float4*)(sm + OFF_W1))[i] = ((const float4*)W1)[i];
    for (int i = tid; i < 192; i += CTA_THREADS)
        ((float4*)(sm + OFF_W))[i] = ((const float4*)W)[i];
    for (int i = tid; i < 64; i += CTA_THREADS)
        ((float4*)(sm + OFF_B))[i] = ((const float4*)b)[i];
    for (int i = tid; i < 16; i += CTA_THREADS)
        ((float4*)(sm + OFF_B1))[i] = ((const float4*)b1)[i];
    for (int i = tid; i < 80; i += CTA_THREADS)
        ((float4*)(sm + OFF_W2))[i] = ((const float4*)W2)[i];
    if (tid < 8) sm[OFF_B2 + tid] = (tid < 5) ? b2[tid] : 0.0f;
    __syncthreads();

    int lane = tid & 31;
    int wid  = tid >> 5;

    float* const hbase = sm + OFF_H + wid * (ROWS_PER_WARP * 128); // duplicated h rows
    const float* Ubase = sm + OFF_U + 2 * lane;

    // shared-space byte addresses for per-t-step W/b reloads (transient regs)
    unsigned Wsh = (unsigned)__cvta_generic_to_shared(sm + OFF_W + 2 * lane);
    unsigned Bsh = (unsigned)__cvta_generic_to_shared(sm + OFF_B + 2 * lane);

    // ================= persistent work loop: one unit = 8 rows =================
    for (;;) {
        int g = 0;
        if (lane == 0) g = atomicAdd(&g_work, 1);
        g = __shfl_sync(0xffffffffu, g, 0);
        if (g >= NUM_UNITS) break;
        int grpBase = g * ROWS_PER_WARP;

        int lenr[ROWS_PER_WARP];
        unsigned xoff[ROWS_PER_WARP];                   // 32-bit byte offsets
#pragma unroll
        for (int r = 0; r < ROWS_PER_WARP; ++r) {
            int row  = g_perm[grpBase + r];
            lenr[r]  = g_len[row];
            xoff[r]  = (unsigned)row * (TSTEPS * FEAT * 4u);
        }
        int tmax = lenr[0];   // descending sort: first row of group is longest

        // zero h slots + c state
        float c0[ROWS_PER_WARP], c1[ROWS_PER_WARP];
#pragma unroll
        for (int r = 0; r < ROWS_PER_WARP; ++r) {
            c0[r] = 0.f; c1[r] = 0.f;
            *reinterpret_cast<float4*>(hbase + r * 128 + 4 * lane) =
                make_float4(0.f, 0.f, 0.f, 0.f);
        }
        __syncwarp();

        // ================= recurrence =================
        for (int t = 0; t < tmax; ++t) {
            // per-t-step W/b reload (transient; asm volatile blocks hoisting)
            unsigned long long wp0[4], wp1[4], wp2[4], bpq[4];
#pragma unroll
            for (int q = 0; q < 4; ++q) {
                wp0[q] = lds64v(Wsh + (0 * GATES + q * UNITSN) * 4u);
                wp1[q] = lds64v(Wsh + (1 * GATES + q * UNITSN) * 4u);
                wp2[q] = lds64v(Wsh + (2 * GATES + q * UNITSN) * 4u);
                bpq[q] = lds64v(Bsh + (q * UNITSN) * 4u);
            }

            unsigned long long z[ROWS_PER_WARP][4];
#pragma unroll
            for (int r = 0; r < ROWS_PER_WARP; ++r) {
                const float* p = (const float*)((const char*)x + xoff[r]) + t * 3;
                unsigned long long d0 = dup2(p[0]);
                unsigned long long d1 = dup2(p[1]);
                unsigned long long d2 = dup2(p[2]);
#pragma unroll
                for (int q = 0; q < 4; ++q) {
                    unsigned long long a = fma2(d0, wp0[q], bpq[q]);
                    a = fma2(d1, wp1[q], a);
                    z[r][q] = fma2(d2, wp2[q], a);
                }
            }

#pragma unroll 4
            for (int k = 0; k < UNITSN; k += 2) {
                const float* Uk = Ubase + k * GATES;
                unsigned long long u00 = ld64(Uk + 0);
                unsigned long long u01 = ld64(Uk + 64);
                unsigned long long u02 = ld64(Uk + 128);
                unsigned long long u03 = ld64(Uk + 192);
                unsigned long long u10 = ld64(Uk + 256);
                unsigned long long u11 = ld64(Uk + 320);
                unsigned long long u12 = ld64(Uk + 384);
                unsigned long long u13 = ld64(Uk + 448);
#pragma unroll
                for (int r = 0; r < ROWS_PER_WARP; ++r) {
                    ulonglong2 hh = *reinterpret_cast<const ulonglong2*>(
                        hbase + r * 128 + 2 * k);        // uniform -> broadcast
                    z[r][0] = fma2(hh.x, u00, z[r][0]);
                    z[r][1] = fma2(hh.x, u01, z[r][1]);
                    z[r][2] = fma2(hh.x, u02, z[r][2]);
                    z[r][3] = fma2(hh.x, u03, z[r][3]);
                    z[r][0] = fma2(hh.y, u10, z[r][0]);
                    z[r][1] = fma2(hh.y, u11, z[r][1]);
                    z[r][2] = fma2(hh.y, u12, z[r][2]);
                    z[r][3] = fma2(hh.y, u13, z[r][3]);
                }
            }

            __syncwarp();   // all lanes done reading h before anyone rewrites it
#pragma unroll
            for (int r = 0; r < ROWS_PER_WARP; ++r) {
                if (t < lenr[r]) {    // mask from precomputed length (no x dep)
                    float2 zi = unpk(z[r][0]);
                    float2 zf = unpk(z[r][1]);
                    float2 zg = unpk(z[r][2]);
                    float2 zo = unpk(z[r][3]);

                    // combined-RCP gates: i,f share one rcp; o and tanh(g)
                    // share one rcp. |z| <~ 8 so products stay finite.
                    float ai0 = 1.0f + __expf(-zi.x), af0 = 1.0f + __expf(-zf.x);
                    float ai1 = 1.0f + __expf(-zi.y), af1 = 1.0f + __expf(-zf.y);
                    float r0if = rcpa(ai0 * af0);
                    float r1if = rcpa(ai1 * af1);
                    float i0 = af0 * r0if, f0 = ai0 * r0if;
                    float i1 = af1 * r1if, f1 = ai1 * r1if;

                    float ao0 = 1.0f + __expf(-zo.x), dg0 = 1.0f + __expf(2.0f * zg.x);
                    float ao1 = 1.0f + __expf(-zo.y), dg1 = 1.0f + __expf(2.0f * zg.y);
                    float r0og = rcpa(ao0 * dg0);
                    float r1og = rcpa(ao1 * dg1);
                    float o0 = dg0 * r0og, g0 = fmaf(-2.0f * ao0, r0og, 1.0f);
                    float o1 = dg1 * r1og, g1 = fmaf(-2.0f * ao1, r1og, 1.0f);

                    c0[r] = f0 * c0[r] + i0 * g0;
                    c1[r] = f1 * c1[r] + i1 * g1;
                    float tc0 = fmaf(-2.0f, rcpa(1.0f + __expf(2.0f * c0[r])), 1.0f);
                    float tc1 = fmaf(-2.0f, rcpa(1.0f + __expf(2.0f * c1[r])), 1.0f);
                    float h0 = o0 * tc0;
                    float h1 = o1 * tc1;
                    *reinterpret_cast<float4*>(hbase + r * 128 + 4 * lane) =
                        make_float4(h0, h0, h1, h1);
                }
            }
            __syncwarp();   // writes visible before next step's reads
        }

        // ================= MLP head + softmax =================
        __syncwarp();
#pragma unroll 1
        for (int r = 0; r < ROWS_PER_WARP; ++r) {
            float* hr = hbase + r * 128;
            unsigned long long acc = ld64(sm + OFF_B1 + 2 * lane);
#pragma unroll 8
            for (int k = 0; k < UNITSN; ++k) {
                unsigned long long hd = ld64(hr + 2 * k);                   // (h[k],h[k])
                unsigned long long w  = ld64(sm + OFF_W1 + k * UNITSN + 2 * lane);
                acc = fma2(hd, w, acc);
            }
            float2 a = unpk(acc);
            float a0 = fmaxf(a.x, 0.f);
            float a1 = fmaxf(a.y, 0.f);
            __syncwarp();
            *reinterpret_cast<float4*>(hr + 4 * lane) = make_float4(a0, a0, a1, a1);
            __syncwarp();

            float logit = 0.0f;
            if (lane < 5) {
                logit = sm[OFF_B2 + lane];
#pragma unroll 8
                for (int k = 0; k < UNITSN; ++k)
                    logit += hr[2 * k] * sm[OFF_W2 + k * 5 + lane];
            }
            float v[5];
#pragma unroll
            for (int j = 0; j < 5; ++j) v[j] = __shfl_sync(0xffffffffu, logit, j);
            float mx = v[0];
#pragma unroll
            for (int j = 1; j < 5; ++j) mx = fmaxf(mx, v[j]);
            float s = 0.0f;
#pragma unroll
            for (int j = 0; j < 5; ++j) { v[j] = __expf(v[j] - mx); s += v[j]; }
            if (lane < 5) {
                int row = g_perm[grpBase + r];   // reload (cold path, saves regs)
                out[(size_t)row * 5 + lane] = __fdividef(v[lane], s);
            }
            __syncwarp();
        }
    }
}

// ============================ launch ============================

extern "C" void kernel_launch(void* const* d_in, const int* in_sizes, int n_in,
                              void* d_out, int out_size) {
    const float* x  = (const float*)d_in[0];
    const float* W  = (const float*)d_in[1];
    const float* U  = (const float*)d_in[2];
    const float* b  = (const float*)d_in[3];
    const float* W1 = (const float*)d_in[4];
    const float* b1 = (const float*)d_in[5];
    const float* W2 = (const float*)d_in[6];
    const float* b2 = (const float*)d_in[7];
    float* out = (float*)d_out;

    (void)in_sizes; (void)n_in; (void)out_size;

    cudaFuncSetAttribute(lstm_main, cudaFuncAttributeMaxDynamicSharedMemorySize,
                         SMEM_BYTES);

    k_len    <<<B_TOTAL / 4, 128>>>(x);
    k_sort   <<<1, 256>>>();
    k_pad    <<<1, 32>>>();
    lstm_main<<<GRID_CTAS, CTA_THREADS, SMEM_BYTES>>>(x, W, U, b, W1, b1, W2, b2, out);
}

// round 12
// speedup vs baseline: 1.2312x; 1.2116x over previous
#include <cuda_runtime.h>
#include <cstdint>

#define UNITSN   64
#define GATES    256        // 4*UNITS
#define TSTEPS   100
#define FEAT     3
#define B_TOTAL  16384

#define CTA_THREADS    320                         // 10 warps, 1 CTA/SM, 204-reg cap
#define WARPS_PER_CTA  10
#define ROWS_PER_WARP  4                           // small R -> small z state, no spills
#define NUM_UNITS      (B_TOTAL / ROWS_PER_WARP)   // 4096 work units
#define GRID_CTAS      148                         // persistent, 1 per SM

// ---- shared memory layout (floats) ----
#define OFF_U    0            // 64*256      = 16384
#define OFF_W1   16384        // 64*64       = 4096
#define OFF_W    20480        // 3*256       = 768
#define OFF_B    21248        // 256
#define OFF_B1   21504        // 64
#define OFF_W2   21568        // 64*5        = 320
#define OFF_B2   21888        // 8 (padded)
#define OFF_H    21896        // 40 rows * 128 (duplicated h) = 5120
#define SMEM_FLOATS 27016
#define SMEM_BYTES  (SMEM_FLOATS * 4)   // 108064 B

// ---- scratch (device globals; no allocation) ----
__device__ int g_len[B_TOTAL];
__device__ int g_perm[B_TOTAL];
__device__ int g_work;

// ---- f32x2 helpers ----
__device__ __forceinline__ unsigned long long fma2(unsigned long long a,
                                                   unsigned long long b,
                                                   unsigned long long c) {
    unsigned long long d;
    asm("fma.rn.f32x2 %0, %1, %2, %3;" : "=l"(d) : "l"(a), "l"(b), "l"(c));
    return d;
}
__device__ __forceinline__ unsigned long long dup2(float v) {
    unsigned long long d;
    asm("mov.b64 %0, {%1, %1};" : "=l"(d) : "f"(v));
    return d;
}
__device__ __forceinline__ float2 unpk(unsigned long long v) {
    float2 r;
    asm("mov.b64 {%0, %1}, %2;" : "=f"(r.x), "=f"(r.y) : "l"(v));
    return r;
}
__device__ __forceinline__ unsigned long long ld64(const float* p) {
    return *reinterpret_cast<const unsigned long long*>(p);
}
__device__ __forceinline__ float rcpa(float x) {
    float y; asm("rcp.approx.f32 %0, %1;" : "=f"(y) : "f"(x)); return y;
}

// ============================ pre-pass kernels ============================

// one warp per row: compute active length (last masked-true step + 1)
__global__ void k_len(const float* __restrict__ x) {
    int lane = threadIdx.x & 31;
    int wid  = threadIdx.x >> 5;
    int row  = blockIdx.x * 4 + wid;
    const float* p = x + (size_t)row * (TSTEPS * FEAT);

    auto chk = [&](int t) -> bool {
        return (p[t * 3] != 0.0f) | (p[t * 3 + 1] != 0.0f) | (p[t * 3 + 2] != 0.0f);
    };
    unsigned m0 = __ballot_sync(0xffffffffu, chk(lane));
    unsigned m1 = __ballot_sync(0xffffffffu, chk(lane + 32));
    unsigned m2 = __ballot_sync(0xffffffffu, chk(lane + 64));
    unsigned m3 = __ballot_sync(0xffffffffu, (lane + 96 < TSTEPS) ? chk(lane + 96) : false);

    if (lane == 0) {
        int len = 0;
        if      (m3) len = 96 + 32 - __clz(m3);
        else if (m2) len = 64 + 32 - __clz(m2);
        else if (m1) len = 32 + 32 - __clz(m1);
        else if (m0) len =      32 - __clz(m0);
        g_len[row] = len;
    }
}

// single CTA: counting-sort rows by descending length into g_perm; reset g_work
__global__ void k_sort() {
    __shared__ int hist[104];
    __shared__ int cur[104];
    int tid = threadIdx.x;   // 256 threads

    if (tid < 104) hist[tid] = 0;
    __syncthreads();
    for (int r = tid; r < B_TOTAL; r += 256)
        atomicAdd(&hist[100 - g_len[r]], 1);
    __syncthreads();
    if (tid == 0) {
        int run = 0;
        for (int k = 0; k <= 100; ++k) { cur[k] = run; run += hist[k]; }
        g_work = 0;
    }
    __syncthreads();
    for (int r = tid; r < B_TOTAL; r += 256) {
        int pos = atomicAdd(&cur[100 - g_len[r]], 1);
        g_perm[pos] = r;
    }
}

// padding no-op: keeps lstm_main at absolute launch index 3 (0-based) so the
// ncu capture lands on lstm_main.
__global__ void k_pad() {}

// ============================ main LSTM kernel ============================

__global__ __launch_bounds__(CTA_THREADS)   // 320 thr -> ~204-reg cap (spill-free)
void lstm_main(const float* __restrict__ x,  const float* __restrict__ W,
               const float* __restrict__ U,  const float* __restrict__ b,
               const float* __restrict__ W1, const float* __restrict__ b1,
               const float* __restrict__ W2, const float* __restrict__ b2,
               float* __restrict__ out) {
    extern __shared__ float sm[];
    int tid = threadIdx.x;

    // ---- cooperative smem staging (once per persistent CTA) ----
    for (int i = tid; i < 4096; i += CTA_THREADS)
        ((float4*)(sm + OFF_U))[i] = ((const float4*)U)[i];
    for (int i = tid; i < 1024; i += CTA_THREADS)
        ((float4*)(sm + OFF_W1))[i] = ((const float4*)W1)[i];
    for (int i = tid; i < 192; i += CTA_THREADS)
        ((float4*)(sm + OFF_W))[i] = ((const float4*)W)[i];
    for (int i = tid; i < 64; i += CTA_THREADS)
        ((float4*)(sm + OFF_B))[i] = ((const float4*)b)[i];
    for (int i = tid; i < 16; i += CTA_THREADS)
        ((float4*)(sm + OFF_B1))[i] = ((const float4*)b1)[i];
    for (int i = tid; i < 80; i += CTA_THREADS)
        ((float4*)(sm + OFF_W2))[i] = ((const float4*)W2)[i];
    if (tid < 8) sm[OFF_B2 + tid] = (tid < 5) ? b2[tid] : 0.0f;
    __syncthreads();

    int lane = tid & 31;
    int wid  = tid >> 5;

    float* const hbase = sm + OFF_H + wid * (ROWS_PER_WARP * 128); // duplicated h rows
    const float* Ubase = sm + OFF_U + 2 * lane;

    // ---- hoist W pairs and b pairs into registers (fits easily at R=4) ----
    unsigned long long Wp[3][4], bp[4];
#pragma unroll
    for (int f = 0; f < 3; ++f)
#pragma unroll
        for (int q = 0; q < 4; ++q)
            Wp[f][q] = ld64(sm + OFF_W + f * GATES + q * UNITSN + 2 * lane);
#pragma unroll
    for (int q = 0; q < 4; ++q)
        bp[q] = ld64(sm + OFF_B + q * UNITSN + 2 * lane);

    // ================= persistent work loop: one unit = 4 rows =================
    for (;;) {
        int g = 0;
        if (lane == 0) g = atomicAdd(&g_work, 1);
        g = __shfl_sync(0xffffffffu, g, 0);
        if (g >= NUM_UNITS) break;
        int grpBase = g * ROWS_PER_WARP;

        int lenr[ROWS_PER_WARP];
        const float* xb[ROWS_PER_WARP];
#pragma unroll
        for (int r = 0; r < ROWS_PER_WARP; ++r) {
            int row  = g_perm[grpBase + r];
            lenr[r]  = g_len[row];
            xb[r]    = x + (size_t)row * (TSTEPS * FEAT);
        }
        int tmax = lenr[0];   // descending sort: first row of group is longest

        // zero h slots + c state
        float c0[ROWS_PER_WARP], c1[ROWS_PER_WARP];
#pragma unroll
        for (int r = 0; r < ROWS_PER_WARP; ++r) {
            c0[r] = 0.f; c1[r] = 0.f;
            *reinterpret_cast<float4*>(hbase + r * 128 + 4 * lane) =
                make_float4(0.f, 0.f, 0.f, 0.f);
        }
        __syncwarp();

        // ================= recurrence =================
        for (int t = 0; t < tmax; ++t) {
            unsigned long long z[ROWS_PER_WARP][4];
#pragma unroll
            for (int r = 0; r < ROWS_PER_WARP; ++r) {
                const float* p = xb[r] + t * 3;          // L1-resident after t=0
                unsigned long long d0 = dup2(p[0]);
                unsigned long long d1 = dup2(p[1]);
                unsigned long long d2 = dup2(p[2]);
#pragma unroll
                for (int q = 0; q < 4; ++q) {
                    unsigned long long a = fma2(d0, Wp[0][q], bp[q]);
                    a = fma2(d1, Wp[1][q], a);
                    z[r][q] = fma2(d2, Wp[2][q], a);
                }
            }

#pragma unroll 4
            for (int k = 0; k < UNITSN; k += 2) {
                const float* Uk = Ubase + k * GATES;
                unsigned long long u00 = ld64(Uk + 0);
                unsigned long long u01 = ld64(Uk + 64);
                unsigned long long u02 = ld64(Uk + 128);
                unsigned long long u03 = ld64(Uk + 192);
                unsigned long long u10 = ld64(Uk + 256);
                unsigned long long u11 = ld64(Uk + 320);
                unsigned long long u12 = ld64(Uk + 384);
                unsigned long long u13 = ld64(Uk + 448);
#pragma unroll
                for (int r = 0; r < ROWS_PER_WARP; ++r) {
                    ulonglong2 hh = *reinterpret_cast<const ulonglong2*>(
                        hbase + r * 128 + 2 * k);        // uniform -> broadcast
                    z[r][0] = fma2(hh.x, u00, z[r][0]);
                    z[r][1] = fma2(hh.x, u01, z[r][1]);
                    z[r][2] = fma2(hh.x, u02, z[r][2]);
                    z[r][3] = fma2(hh.x, u03, z[r][3]);
                    z[r][0] = fma2(hh.y, u10, z[r][0]);
                    z[r][1] = fma2(hh.y, u11, z[r][1]);
                    z[r][2] = fma2(hh.y, u12, z[r][2]);
                    z[r][3] = fma2(hh.y, u13, z[r][3]);
                }
            }

            __syncwarp();   // all lanes done reading h before anyone rewrites it
#pragma unroll
            for (int r = 0; r < ROWS_PER_WARP; ++r) {
                if (t < lenr[r]) {    // mask from precomputed length (no x dep)
                    float2 zi = unpk(z[r][0]);
                    float2 zf = unpk(z[r][1]);
                    float2 zg = unpk(z[r][2]);
                    float2 zo = unpk(z[r][3]);

                    // combined-RCP gates: i,f share one rcp; o and tanh(g)
                    // share one rcp. |z| <~ 8 so products stay finite.
                    float ai0 = 1.0f + __expf(-zi.x), af0 = 1.0f + __expf(-zf.x);
                    float ai1 = 1.0f + __expf(-zi.y), af1 = 1.0f + __expf(-zf.y);
                    float r0if = rcpa(ai0 * af0);
                    float r1if = rcpa(ai1 * af1);
                    float i0 = af0 * r0if, f0 = ai0 * r0if;
                    float i1 = af1 * r1if, f1 = ai1 * r1if;

                    float ao0 = 1.0f + __expf(-zo.x), dg0 = 1.0f + __expf(2.0f * zg.x);
                    float ao1 = 1.0f + __expf(-zo.y), dg1 = 1.0f + __expf(2.0f * zg.y);
                    float r0og = rcpa(ao0 * dg0);
                    float r1og = rcpa(ao1 * dg1);
                    float o0 = dg0 * r0og, g0 = fmaf(-2.0f * ao0, r0og, 1.0f);
                    float o1 = dg1 * r1og, g1 = fmaf(-2.0f * ao1, r1og, 1.0f);

                    c0[r] = f0 * c0[r] + i0 * g0;
                    c1[r] = f1 * c1[r] + i1 * g1;
                    float tc0 = fmaf(-2.0f, rcpa(1.0f + __expf(2.0f * c0[r])), 1.0f);
                    float tc1 = fmaf(-2.0f, rcpa(1.0f + __expf(2.0f * c1[r])), 1.0f);
                    float h0 = o0 * tc0;
                    float h1 = o1 * tc1;
                    *reinterpret_cast<float4*>(hbase + r * 128 + 4 * lane) =
                        make_float4(h0, h0, h1, h1);
                }
            }
            __syncwarp();   // writes visible before next step's reads
        }

        // ================= MLP head + softmax =================
        __syncwarp();
#pragma unroll 1
        for (int r = 0; r < ROWS_PER_WARP; ++r) {
            float* hr = hbase + r * 128;
            unsigned long long acc = ld64(sm + OFF_B1 + 2 * lane);
#pragma unroll 8
            for (int k = 0; k < UNITSN; ++k) {
                unsigned long long hd = ld64(hr + 2 * k);                   // (h[k],h[k])
                unsigned long long w  = ld64(sm + OFF_W1 + k * UNITSN + 2 * lane);
                acc = fma2(hd, w, acc);
            }
            float2 a = unpk(acc);
            float a0 = fmaxf(a.x, 0.f);
            float a1 = fmaxf(a.y, 0.f);
            __syncwarp();
            *reinterpret_cast<float4*>(hr + 4 * lane) = make_float4(a0, a0, a1, a1);
            __syncwarp();

            float logit = 0.0f;
            if (lane < 5) {
                logit = sm[OFF_B2 + lane];
#pragma unroll 8
                for (int k = 0; k < UNITSN; ++k)
                    logit += hr[2 * k] * sm[OFF_W2 + k * 5 + lane];
            }
            float v[5];
#pragma unroll
            for (int j = 0; j < 5; ++j) v[j] = __shfl_sync(0xffffffffu, logit, j);
            float mx = v[0];
#pragma unroll
            for (int j = 1; j < 5; ++j) mx = fmaxf(mx, v[j]);
            float s = 0.0f;
#pragma unroll
            for (int j = 0; j < 5; ++j) { v[j] = __expf(v[j] - mx); s += v[j]; }
            if (lane < 5) {
                int row = g_perm[grpBase + r];   // reload (cold path, saves regs)
                out[(size_t)row * 5 + lane] = __fdividef(v[lane], s);
            }
            __syncwarp();
        }
    }
}

// ============================ launch ============================

extern "C" void kernel_launch(void* const* d_in, const int* in_sizes, int n_in,
                              void* d_out, int out_size) {
    const float* x  = (const float*)d_in[0];
    const float* W  = (const float*)d_in[1];
    const float* U  = (const float*)d_in[2];
    const float* b  = (const float*)d_in[3];
    const float* W1 = (const float*)d_in[4];
    const float* b1 = (const float*)d_in[5];
    const float* W2 = (const float*)d_in[6];
    const float* b2 = (const float*)d_in[7];
    float* out = (float*)d_out;

    (void)in_sizes; (void)n_in; (void)out_size;

    cudaFuncSetAttribute(lstm_main, cudaFuncAttributeMaxDynamicSharedMemorySize,
                         SMEM_BYTES);

    k_len    <<<B_TOTAL / 4, 128>>>(x);
    k_sort   <<<1, 256>>>();
    k_pad    <<<1, 32>>>();
    lstm_main<<<GRID_CTAS, CTA_THREADS, SMEM_BYTES>>>(x, W, U, b, W1, b1, W2, b2, out);
}

// round 16
// speedup vs baseline: 1.5506x; 1.2594x over previous
#include <cuda_runtime.h>
#include <cuda_bf16.h>
#include <cstdint>

#define UNITSN   64
#define GATES    256
#define TSTEPS   100
#define FEAT     3
#define B_TOTAL  16384

#define CTA_THREADS  192                    // 6 warps -> 341-reg cap, no spills
#define WARPS_PER_CTA 6
#define ROWS_PER_WARP 16
#define NUM_UNITS    (B_TOTAL / ROWS_PER_WARP)   // 1024
#define GRID_CTAS    148

// K layout: [hh*Uh 64 | hh*Ul 64 | hl*Uh 64 | aug 16] = 208 = 13 k-tiles
#define K_TILES  13
#define N_TILES  32

// ---- shared memory layout (float offsets) ----
#define OFF_BPERM 0            // 13*32 tiles * 64 words = 26624
#define OFF_W1    26624        // 4096
#define OFF_W2    30720        // 320
#define OFF_B1    31040        // 64
#define OFF_B2    31104        // 8
#define OFF_STAGE 31112        // 6 warps * (17*64) = 6528
#define SMEM_FLOATS 37640
#define SMEM_BYTES  (SMEM_FLOATS * 4)       // 150560 B

// ---- scratch ----
__device__ int g_len[B_TOTAL];
__device__ int g_perm[B_TOTAL];
__device__ int g_work;

// ---- helpers ----
__device__ __forceinline__ unsigned short bfbits(float v) {
    return __bfloat16_as_ushort(__float2bfloat16(v));
}
__device__ __forceinline__ float bf2f(unsigned short u) {
    return __bfloat162float(__ushort_as_bfloat16(u));
}
__device__ __forceinline__ uint32_t pack2(unsigned short lo, unsigned short hi) {
    return (uint32_t)lo | ((uint32_t)hi << 16);
}
__device__ __forceinline__ float rcpa(float x) {
    float y; asm("rcp.approx.f32 %0, %1;" : "=f"(y) : "f"(x)); return y;
}
__device__ __forceinline__ void mma16816(float& d0, float& d1, float& d2, float& d3,
                                         uint32_t a0, uint32_t a1, uint32_t a2, uint32_t a3,
                                         uint32_t b0, uint32_t b1) {
    asm volatile("mma.sync.aligned.m16n8k16.row.col.f32.bf16.bf16.f32 "
                 "{%0,%1,%2,%3}, {%4,%5,%6,%7}, {%8,%9}, {%0,%1,%2,%3};"
                 : "+f"(d0), "+f"(d1), "+f"(d2), "+f"(d3)
                 : "r"(a0), "r"(a1), "r"(a2), "r"(a3), "r"(b0), "r"(b1));
}

// B element (bf16 bits) for K-slot k, gate n
__device__ unsigned short bbits(int k, int n, const float* U, const float* W,
                                const float* b) {
    if (k < 64)  return bfbits(U[k * GATES + n]);                       // Uh (vs hh)
    if (k < 128) { float v = U[(k - 64) * GATES + n];                   // Ul (vs hh)
                   return bfbits(v - bf2f(bfbits(v))); }
    if (k < 192) return bfbits(U[(k - 128) * GATES + n]);               // Uh (vs hl)
    if (k < 195) return bfbits(W[(k - 192) * GATES + n]);               // Wh (vs xh)
    if (k < 198) return bfbits(W[(k - 195) * GATES + n]);               // Wh (vs xl)
    if (k < 201) { float v = W[(k - 198) * GATES + n];                  // Wl (vs xh)
                   return bfbits(v - bf2f(bfbits(v))); }
    if (k == 201) return bfbits(b[n]);                                  // bh (vs 1)
    if (k == 202) { float v = b[n]; return bfbits(v - bf2f(bfbits(v))); } // bl (vs 1)
    return 0;
}

// ============================ pre-pass kernels ============================
__global__ void k_len(const float* __restrict__ x) {
    int lane = threadIdx.x & 31, wid = threadIdx.x >> 5;
    int row = blockIdx.x * 4 + wid;
    const float* p = x + (size_t)row * (TSTEPS * FEAT);
    auto chk = [&](int t) -> bool {
        return (p[t*3] != 0.f) | (p[t*3+1] != 0.f) | (p[t*3+2] != 0.f);
    };
    unsigned m0 = __ballot_sync(~0u, chk(lane));
    unsigned m1 = __ballot_sync(~0u, chk(lane + 32));
    unsigned m2 = __ballot_sync(~0u, chk(lane + 64));
    unsigned m3 = __ballot_sync(~0u, (lane + 96 < TSTEPS) ? chk(lane + 96) : false);
    if (lane == 0) {
        int len = 0;
        if      (m3) len = 128 - __clz(m3);
        else if (m2) len =  96 - __clz(m2);
        else if (m1) len =  64 - __clz(m1);
        else if (m0) len =  32 - __clz(m0);
        g_len[row] = len;
    }
}

__global__ void k_sort() {
    __shared__ int hist[104], cur[104];
    int tid = threadIdx.x;
    if (tid < 104) hist[tid] = 0;
    __syncthreads();
    for (int r = tid; r < B_TOTAL; r += 256) atomicAdd(&hist[100 - g_len[r]], 1);
    __syncthreads();
    if (tid == 0) {
        int run = 0;
        for (int k = 0; k <= 100; ++k) { cur[k] = run; run += hist[k]; }
        g_work = 0;
    }
    __syncthreads();
    for (int r = tid; r < B_TOTAL; r += 256) {
        int pos = atomicAdd(&cur[100 - g_len[r]], 1);
        g_perm[pos] = r;
    }
}

__global__ void k_pad() {}   // keeps main kernel at ncu's captured launch index

// ============================ mma.sync LSTM ============================
__global__ __launch_bounds__(CTA_THREADS)
void lstm_mma(const float* __restrict__ x,  const float* __restrict__ W,
              const float* __restrict__ U,  const float* __restrict__ b,
              const float* __restrict__ W1, const float* __restrict__ b1,
              const float* __restrict__ W2, const float* __restrict__ b2,
              float* __restrict__ out) {
    extern __shared__ float sm[];
    int tid  = threadIdx.x;
    int lane = tid & 31;
    int wid  = tid >> 5;
    int gq   = lane >> 2;      // mma group 0..7 (row within half-tile, D/A col group)
    int tg   = lane & 3;       // thread-in-group (k/n pair selector)

    // ---- build permuted B fragments: tile (kt,nt) -> 64 words, lane*2 {b0,b1} ----
    // b0 = (B[k0][n], B[k0+1][n]), b1 = (B[k0+8][n], B[k0+9][n]); k0=kt*16+2tg, n=nt*8+gq
    uint32_t* bp32 = reinterpret_cast<uint32_t*>(sm + OFF_BPERM);
    for (int e = tid; e < K_TILES * N_TILES * 32; e += CTA_THREADS) {
        int le = e & 31, nt = (e >> 5) & 31, kt = e >> 10;
        int etg = le & 3, egq = le >> 2;
        int n  = nt * 8 + egq;
        int k0 = kt * 16 + 2 * etg;
        bp32[(kt * 32 + nt) * 64 + le * 2 + 0] =
            pack2(bbits(k0,     n, U, W, b), bbits(k0 + 1, n, U, W, b));
        bp32[(kt * 32 + nt) * 64 + le * 2 + 1] =
            pack2(bbits(k0 + 8, n, U, W, b), bbits(k0 + 9, n, U, W, b));
    }
    // ---- head weights into smem ----
    for (int i = tid; i < 4096; i += CTA_THREADS) sm[OFF_W1 + i] = W1[i];
    for (int i = tid; i < 320;  i += CTA_THREADS) sm[OFF_W2 + i] = W2[i];
    for (int i = tid; i < 64;   i += CTA_THREADS) sm[OFF_B1 + i] = b1[i];
    if (tid < 8) sm[OFF_B2 + tid] = (tid < 5) ? b2[tid] : 0.0f;
    __syncthreads();

    const unsigned long long* bp =
        reinterpret_cast<const unsigned long long*>(sm + OFF_BPERM);
    float* stg = sm + OFF_STAGE + wid * (17 * 64);
    const unsigned short one_b = bfbits(1.0f);

    // ================= persistent work loop: one unit = 16 rows =================
    for (;;) {
        int g = 0;
        if (lane == 0) g = atomicAdd(&g_work, 1);
        g = __shfl_sync(~0u, g, 0);
        if (g >= NUM_UNITS) break;
        int base = g * ROWS_PER_WARP;

        int rowg  = g_perm[base + gq];
        int rowg8 = g_perm[base + gq + 8];
        int leng  = g_len[rowg];
        int len8  = g_len[rowg8];
        int tmax  = g_len[g_perm[base]];         // sorted desc within unit
        const float* xg  = x + (size_t)rowg  * (TSTEPS * FEAT);
        const float* xg8 = x + (size_t)rowg8 * (TSTEPS * FEAT);

        float c[32];                             // [rh*16 + m*2 + e]
        uint32_t aHH[4][4], aHL[4][4];           // A frags for h hi / lo
#pragma unroll
        for (int i = 0; i < 32; ++i) c[i] = 0.f;
#pragma unroll
        for (int kt = 0; kt < 4; ++kt)
#pragma unroll
            for (int j = 0; j < 4; ++j) { aHH[kt][j] = 0u; aHL[kt][j] = 0u; }

        for (int t = 0; t < tmax; ++t) {
            // ---- aug A fragment (x hi/lo + ones), per-thread ----
            float xv0 = xg[t*3], xv1 = xg[t*3+1], xv2 = xg[t*3+2];
            float yv0 = xg8[t*3], yv1 = xg8[t*3+1], yv2 = xg8[t*3+2];
            unsigned short xh0 = bfbits(xv0), xh1 = bfbits(xv1), xh2 = bfbits(xv2);
            unsigned short yh0 = bfbits(yv0), yh1 = bfbits(yv1), yh2 = bfbits(yv2);
            unsigned short xl0 = bfbits(xv0 - bf2f(xh0));
            unsigned short xl1 = bfbits(xv1 - bf2f(xh1));
            unsigned short xl2 = bfbits(xv2 - bf2f(xh2));
            unsigned short yl0 = bfbits(yv0 - bf2f(yh0));
            unsigned short yl1 = bfbits(yv1 - bf2f(yh1));
            unsigned short yl2 = bfbits(yv2 - bf2f(yh2));
            uint32_t g0, g1, g2, g3;
            if (tg == 0) { g0 = pack2(xh0, xh1); g1 = pack2(yh0, yh1);
                           g2 = pack2(xh2, one_b); g3 = pack2(yh2, one_b); }
            else if (tg == 1) { g0 = pack2(xh2, xl0); g1 = pack2(yh2, yl0);
                                g2 = pack2(one_b, 0); g3 = pack2(one_b, 0); }
            else if (tg == 2) { g0 = pack2(xl1, xl2); g1 = pack2(yl1, yl2);
                                g2 = 0u; g3 = 0u; }
            else { g0 = pack2(xh0, xh1); g1 = pack2(yh0, yh1); g2 = 0u; g3 = 0u; }

            // ---- MMA: D[16x256] = A[16x208] * B ----
            float D[N_TILES][4];
#pragma unroll
            for (int nt = 0; nt < N_TILES; ++nt) {
                D[nt][0] = 0.f; D[nt][1] = 0.f; D[nt][2] = 0.f; D[nt][3] = 0.f;
            }
#pragma unroll
            for (int kt = 0; kt < K_TILES; ++kt) {
                uint32_t a0, a1, a2, a3;
                if (kt < 4)       { a0 = aHH[kt][0];   a1 = aHH[kt][1];
                                    a2 = aHH[kt][2];   a3 = aHH[kt][3]; }
                else if (kt < 8)  { a0 = aHH[kt-4][0]; a1 = aHH[kt-4][1];
                                    a2 = aHH[kt-4][2]; a3 = aHH[kt-4][3]; }
                else if (kt < 12) { a0 = aHL[kt-8][0]; a1 = aHL[kt-8][1];
                                    a2 = aHL[kt-8][2]; a3 = aHL[kt-8][3]; }
                else              { a0 = g0; a1 = g1; a2 = g2; a3 = g3; }
                const unsigned long long* bt = bp + kt * (N_TILES * 32) + lane;
#pragma unroll
                for (int nt = 0; nt < N_TILES; ++nt) {
                    unsigned long long bb = bt[nt * 32];
                    mma16816(D[nt][0], D[nt][1], D[nt][2], D[nt][3],
                             a0, a1, a2, a3,
                             (uint32_t)bb, (uint32_t)(bb >> 32));
                }
            }

            // ---- epilogue: gates, c/h update, repack A frags (no shuffles) ----
#pragma unroll
            for (int m = 0; m < 8; ++m) {
#pragma unroll
                for (int rh = 0; rh < 2; ++rh) {
                    bool act = t < (rh ? len8 : leng);
                    if (act) {
                        float hpair[2];
#pragma unroll
                        for (int e = 0; e < 2; ++e) {
                            int di = rh * 2 + e;
                            float zi = D[m][di],      zf = D[m + 8][di];
                            float zg = D[m + 16][di], zo = D[m + 24][di];
                            float ai = 1.f + __expf(-zi), af = 1.f + __expf(-zf);
                            float rif = rcpa(ai * af);
                            float gi = af * rif, gf = ai * rif;
                            float ao = 1.f + __expf(-zo), dg = 1.f + __expf(2.f * zg);
                            float rog = rcpa(ao * dg);
                            float go = dg * rog, gg = fmaf(-2.f * ao, rog, 1.f);
                            int ci = rh * 16 + m * 2 + e;
                            c[ci] = gf * c[ci] + gi * gg;
                            float th = fmaf(-2.f, rcpa(1.f + __expf(2.f * c[ci])), 1.f);
                            hpair[e] = go * th;
                        }
                        unsigned short h0h = bfbits(hpair[0]), h1h = bfbits(hpair[1]);
                        unsigned short h0l = bfbits(hpair[0] - bf2f(h0h));
                        unsigned short h1l = bfbits(hpair[1] - bf2f(h1h));
                        int kt = m >> 1, j = (m & 1) * 2 + rh;
                        aHH[kt][j] = pack2(h0h, h1h);
                        aHL[kt][j] = pack2(h0l, h1l);
                    }
                }
            }
        }

        // ================= MLP head + softmax =================
        __syncwarp();
        // h = hh + hl into staging [16 rows][64 units]
#pragma unroll
        for (int kt = 0; kt < 4; ++kt)
#pragma unroll
            for (int j = 0; j < 4; ++j) {
                int row = (j & 1) ? (gq + 8) : gq;
                int col = kt * 16 + 2 * tg + ((j >> 1) ? 8 : 0);
                uint32_t ph = aHH[kt][j], pl = aHL[kt][j];
                stg[row * 64 + col]     = bf2f((unsigned short)ph)
                                        + bf2f((unsigned short)pl);
                stg[row * 64 + col + 1] = bf2f((unsigned short)(ph >> 16))
                                        + bf2f((unsigned short)(pl >> 16));
            }
        __syncwarp();
        float* aout = stg + 16 * 64;
        for (int r2 = 0; r2 < ROWS_PER_WARP; ++r2) {
            const float* hr = stg + r2 * 64;
            float a0 = sm[OFF_B1 + 2 * lane], a1 = sm[OFF_B1 + 2 * lane + 1];
#pragma unroll 8
            for (int k = 0; k < UNITSN; ++k) {
                float hk = hr[k];
                a0 = fmaf(hk, sm[OFF_W1 + k * 64 + 2 * lane],     a0);
                a1 = fmaf(hk, sm[OFF_W1 + k * 64 + 2 * lane + 1], a1);
            }
            a0 = fmaxf(a0, 0.f); a1 = fmaxf(a1, 0.f);
            __syncwarp();
            aout[2 * lane] = a0; aout[2 * lane + 1] = a1;
            __syncwarp();
            float logit = 0.f;
            if (lane < 5) {
                logit = sm[OFF_B2 + lane];
#pragma unroll 8
                for (int k = 0; k < UNITSN; ++k)
                    logit += aout[k] * sm[OFF_W2 + k * 5 + lane];
            }
            float v[5];
#pragma unroll
            for (int j = 0; j < 5; ++j) v[j] = __shfl_sync(~0u, logit, j);
            float mx = v[0];
#pragma unroll
            for (int j = 1; j < 5; ++j) mx = fmaxf(mx, v[j]);
            float s = 0.f;
#pragma unroll
            for (int j = 0; j < 5; ++j) { v[j] = __expf(v[j] - mx); s += v[j]; }
            if (lane < 5) {
                int row = g_perm[base + r2];
                out[(size_t)row * 5 + lane] = __fdividef(v[lane], s);
            }
            __syncwarp();
        }
    }
}

// ============================ launch ============================
extern "C" void kernel_launch(void* const* d_in, const int* in_sizes, int n_in,
                              void* d_out, int out_size) {
    const float* x  = (const float*)d_in[0];
    const float* W  = (const float*)d_in[1];
    const float* U  = (const float*)d_in[2];
    const float* b  = (const float*)d_in[3];
    const float* W1 = (const float*)d_in[4];
    const float* b1 = (const float*)d_in[5];
    const float* W2 = (const float*)d_in[6];
    const float* b2 = (const float*)d_in[7];
    float* out = (float*)d_out;
    (void)in_sizes; (void)n_in; (void)out_size;

    cudaFuncSetAttribute(lstm_mma, cudaFuncAttributeMaxDynamicSharedMemorySize,
                         SMEM_BYTES);

    k_len   <<<B_TOTAL / 4, 128>>>(x);
    k_sort  <<<1, 256>>>();
    k_pad   <<<1, 32>>>();
    lstm_mma<<<GRID_CTAS, CTA_THREADS, SMEM_BYTES>>>(x, W, U, b, W1, b1, W2, b2, out);
}